// round 15
// baseline (speedup 1.0000x reference)
#include <cuda_runtime.h>
#include <cuda_fp16.h>
#include <math.h>
#include <stdint.h>

// ---------------------------------------------------------------------------
// GPT-2 small forward:  B=2, S=1024, L=4, H=12, E=768, D=64, V=50257
// GEMMs via mma.sync.m16n8k16.f16 with fp16 split operands:
//   layer GEMMs: 3-term (Ah@Bh + Ah@Bl + Al@Bh), err ~2^-22
//   LM head:     2-term (Ah@B + Al@B), B single fp16 (verified: 2.08e-4)
// This round: per-GEMM best tiles, FC2 split-K=3, attention TK=64.
// ---------------------------------------------------------------------------
#define BB 2
#define SS 1024
#define LL 4
#define HH 12
#define EE 768
#define VV 50257
#define DD 64
#define MM (BB*SS)
#define NPADLM 50432        // VV padded to multiple of 256

// Scratch (device globals: allocation-free rule)
__device__ float g_X  [MM * EE];
__device__ float g_QKV[MM * 3 * EE];
__device__ float g_P  [3 * MM * EE];                 // split-K partials
__device__ __align__(256) __half g_Ah[MM * EE];
__device__ __align__(256) __half g_Al[MM * EE];
__device__ __align__(256) __half g_Fh[MM * 4 * EE];
__device__ __align__(256) __half g_Fl[MM * 4 * EE];
__device__ __align__(256) __half g_Wh[4 * EE * EE];
__device__ __align__(256) __half g_Wl[4 * EE * EE];
__device__ __align__(256) __half g_LMW[(size_t)NPADLM * EE];

// ---------------------------------------------------------------------------
__device__ __forceinline__ uint32_t smem_u32(const void* p) {
    return (uint32_t)__cvta_generic_to_shared(p);
}
__device__ __forceinline__ void cp16(uint32_t dst, const void* src) {
    asm volatile("cp.async.cg.shared.global [%0], [%1], 16;" :: "r"(dst), "l"(src));
}
__device__ __forceinline__ void mma_f16(float* c, const uint32_t* a, const uint32_t* b) {
    asm volatile(
        "mma.sync.aligned.m16n8k16.row.col.f32.f16.f16.f32 "
        "{%0,%1,%2,%3},{%4,%5,%6,%7},{%8,%9},{%0,%1,%2,%3};"
        : "+f"(c[0]), "+f"(c[1]), "+f"(c[2]), "+f"(c[3])
        : "r"(a[0]), "r"(a[1]), "r"(a[2]), "r"(a[3]), "r"(b[0]), "r"(b[1]));
}
__device__ __forceinline__ void ldmx4(uint32_t* r, uint32_t addr) {
    asm volatile("ldmatrix.sync.aligned.m8n8.x4.shared.b16 {%0,%1,%2,%3}, [%4];"
                 : "=r"(r[0]), "=r"(r[1]), "=r"(r[2]), "=r"(r[3]) : "r"(addr));
}
__device__ __forceinline__ void split_h(float v, __half& hi, __half& lo) {
    hi = __float2half(v);
    lo = __float2half(v - __half2float(hi));
}

// ---------------------------------------------------------------------------
// Embedding
// ---------------------------------------------------------------------------
__global__ void embed_k(const int* __restrict__ tok,
                        const float* __restrict__ wte,
                        const float* __restrict__ wpe,
                        float* __restrict__ X)
{
    int row = blockIdx.x;
    int s   = row & (SS - 1);
    int t   = tok[row];
    const float* we = wte + (size_t)t * EE;
    const float* wp = wpe + (size_t)s * EE;
    float* xr = X + (size_t)row * EE;
    for (int e = threadIdx.x; e < EE; e += blockDim.x)
        xr[e] = we[e] + wp[e];
}

// ---------------------------------------------------------------------------
// LayerNorm -> split fp16 hi/lo
// ---------------------------------------------------------------------------
__global__ __launch_bounds__(256) void ln_split_k(const float* __restrict__ X,
                                                  const float* __restrict__ gam,
                                                  const float* __restrict__ bet,
                                                  __half* __restrict__ Oh,
                                                  __half* __restrict__ Ol)
{
    __shared__ float s1[8], s2[8];
    int row = blockIdx.x, tid = threadIdx.x;
    const float* xr = X + (size_t)row * EE;
    float v[3];
    float sum = 0.f, sq = 0.f;
#pragma unroll
    for (int k = 0; k < 3; k++) {
        v[k] = xr[tid + k * 256];
        sum += v[k];
        sq  += v[k] * v[k];
    }
#pragma unroll
    for (int o = 16; o > 0; o >>= 1) {
        sum += __shfl_xor_sync(0xffffffffu, sum, o);
        sq  += __shfl_xor_sync(0xffffffffu, sq,  o);
    }
    if ((tid & 31) == 0) { s1[tid >> 5] = sum; s2[tid >> 5] = sq; }
    __syncthreads();
    sum = 0.f; sq = 0.f;
#pragma unroll
    for (int i = 0; i < 8; i++) { sum += s1[i]; sq += s2[i]; }
    const float inv_n = 1.0f / (float)EE;
    float mu  = sum * inv_n;
    float var = sq * inv_n - mu * mu;
    float rs  = rsqrtf(var + 1e-5f);
#pragma unroll
    for (int k = 0; k < 3; k++) {
        int e = tid + k * 256;
        float y = (v[k] - mu) * rs * gam[e] + bet[e];
        __half hi, lo; split_h(y, hi, lo);
        Oh[(size_t)row * EE + e] = hi;
        Ol[(size_t)row * EE + e] = lo;
    }
}

// ---------------------------------------------------------------------------
// Weight split+transpose: Bg[K,N] fp32 -> Bh,Bl [N,K] fp16
// ---------------------------------------------------------------------------
__global__ void splitT3_k(const float* __restrict__ Bg,
                          __half* __restrict__ Bh,
                          __half* __restrict__ Bl, int K, int N)
{
    __shared__ float t[32][33];
    int n0 = blockIdx.x * 32, k0 = blockIdx.y * 32;
    int tx = threadIdx.x, ty = threadIdx.y;
#pragma unroll
    for (int i = 0; i < 4; i++)
        t[ty + 8 * i][tx] = Bg[(size_t)(k0 + ty + 8 * i) * N + n0 + tx];
    __syncthreads();
#pragma unroll
    for (int i = 0; i < 4; i++) {
        int n = n0 + ty + 8 * i;
        int k = k0 + tx;
        __half hi, lo; split_h(t[tx][ty + 8 * i], hi, lo);
        Bh[(size_t)n * K + k] = hi;
        Bl[(size_t)n * K + k] = lo;
    }
}

// Single-fp16 transpose with zero pad (LM head weights)
__global__ void splitT1_k(const float* __restrict__ Bg,
                          __half* __restrict__ Bo, int K, int N)
{
    __shared__ float t[32][33];
    int n0 = blockIdx.x * 32, k0 = blockIdx.y * 32;
    int tx = threadIdx.x, ty = threadIdx.y;
#pragma unroll
    for (int i = 0; i < 4; i++) {
        int n = n0 + tx;
        t[ty + 8 * i][tx] = (n < N) ? Bg[(size_t)(k0 + ty + 8 * i) * N + n] : 0.f;
    }
    __syncthreads();
#pragma unroll
    for (int i = 0; i < 4; i++) {
        int n = n0 + ty + 8 * i;
        Bo[(size_t)n * K + k0 + tx] = __float2half(t[tx][ty + 8 * i]);
    }
}

// ---------------------------------------------------------------------------
// Split-K reduce: X += P0 + P1 + P2 + bias
// ---------------------------------------------------------------------------
__global__ void redadd_k(const float* __restrict__ P,
                         const float* __restrict__ bias,
                         float* __restrict__ X)
{
    int idx = blockIdx.x * 256 + threadIdx.x;
    if (idx < MM * EE) {
        int col = idx % EE;
        X[idx] += P[idx] + P[idx + MM * EE] + P[idx + 2 * MM * EE] + bias[col];
    }
}

// ---------------------------------------------------------------------------
// fp16-split GEMM: C[M,N] = A[M,K(ld=Kld)] @ W[N,K]^T over K-span Kiter
// NA/NB split terms; SPLITK: blockIdx.z selects K-part, C offset by z*MM*N.
// ---------------------------------------------------------------------------
#define RS 40
#define KC 32

template<int BM, int BN, int WM, int WN, int NA, int NB, int NSTG,
         bool BIAS, bool GELU, bool RES, bool NGUARD, bool OSPLIT, bool SPLITK>
__global__ void __launch_bounds__(((BM/WM)*(BN/WN))*32)
hgemm(const __half* __restrict__ Ah, const __half* __restrict__ Al,
      const __half* __restrict__ Bh, const __half* __restrict__ Bl,
      const float* __restrict__ bias, const float* __restrict__ res,
      float* __restrict__ C, __half* __restrict__ Oh, __half* __restrict__ Ol,
      int N, int Kld, int Kiter)
{
    constexpr int WARPS_M = BM / WM;
    constexpr int NTHR = WARPS_M * (BN / WN) * 32;
    constexpr int MT = WM / 16, NT = WN / 8;
    constexpr int STG = (NA * BM + NB * BN) * RS;
    constexpr int OAl = BM * RS;
    constexpr int OBh = NA * BM * RS;
    constexpr int OBl = NA * BM * RS + BN * RS;
    constexpr int CH  = (NA * BM + NB * BN) * 4;

    extern __shared__ __half sm[];

    const int tid = threadIdx.x, lane = tid & 31, wid = tid >> 5;
    const int wm = (wid % WARPS_M) * WM, wn = (wid / WARPS_M) * WN;
    const int bm = blockIdx.x * BM, bn = blockIdx.y * BN;
    const int koff = SPLITK ? blockIdx.z * Kiter : 0;
    float* Cp = SPLITK ? (C + (size_t)blockIdx.z * MM * N) : C;

    float acc[MT][NT][4];
#pragma unroll
    for (int i = 0; i < MT; i++)
#pragma unroll
        for (int j = 0; j < NT; j++)
#pragma unroll
            for (int t = 0; t < 4; t++) acc[i][j][t] = 0.f;

    const int nIter = Kiter / KC;

    auto load_stage = [&](int it, int s) {
        const int k0 = koff + it * KC;
#pragma unroll
        for (int t = 0; t < CH / NTHR; t++) {
            int c = tid + t * NTHR;
            int ridx = c >> 2, part = c & 3;
            const __half* g; int off;
            if (NA == 2 && ridx < BM)      { g = Ah + (size_t)(bm + ridx) * Kld; off = ridx * RS; }
            else if (NA == 2 && ridx < 2 * BM)
                { int r = ridx - BM; g = Al + (size_t)(bm + r) * Kld; off = OAl + r * RS; }
            else if (NA == 1 && ridx < BM) { g = Ah + (size_t)(bm + ridx) * Kld; off = ridx * RS; }
            else if (NB == 1 || ridx < NA * BM + BN)
                { int r = ridx - NA * BM; g = Bh + (size_t)(bn + r) * Kld; off = OBh + r * RS; }
            else
                { int r = ridx - NA * BM - BN; g = Bl + (size_t)(bn + r) * Kld; off = OBl + r * RS; }
            cp16(smem_u32(sm + s * STG + off + part * 8), g + k0 + part * 8);
        }
        asm volatile("cp.async.commit_group;");
    };

#pragma unroll
    for (int c = 0; c < NSTG - 1; c++) load_stage(c, c);

    const int a_lane = (wm + (lane & 15)) * RS + ((lane >> 4) << 3);
    const int b_lane = (wn + ((lane >> 4) << 3) + (lane & 7)) * RS + (((lane >> 3) & 1) << 3);

    for (int it = 0; it < nIter; it++) {
        const int s = it % NSTG;
        asm volatile("cp.async.wait_group %0;" :: "n"(NSTG - 2));
        __syncthreads();
        if (it + NSTG - 1 < nIter)
            load_stage(it + NSTG - 1, (it + NSTG - 1) % NSTG);

        const __half* stg = sm + s * STG;
#pragma unroll
        for (int kh = 0; kh < 2; kh++) {
            uint32_t ah[MT][4], al[MT][4];
#pragma unroll
            for (int mt = 0; mt < MT; mt++) {
                ldmx4(ah[mt], smem_u32(stg + a_lane + mt * 16 * RS + kh * 16));
                if (NA == 2)
                    ldmx4(al[mt], smem_u32(stg + OAl + a_lane + mt * 16 * RS + kh * 16));
            }
#pragma unroll
            for (int ntb = 0; ntb < NT / 4; ntb++) {
                uint32_t bh[4][2], bl[4][2];
#pragma unroll
                for (int p = 0; p < 2; p++) {
                    const int nt = ntb * 4 + p * 2;
                    uint32_t r4[4];
                    ldmx4(r4, smem_u32(stg + OBh + b_lane + nt * 8 * RS + kh * 16));
                    bh[p*2][0] = r4[0]; bh[p*2][1] = r4[1];
                    bh[p*2+1][0] = r4[2]; bh[p*2+1][1] = r4[3];
                    if (NB == 2) {
                        ldmx4(r4, smem_u32(stg + OBl + b_lane + nt * 8 * RS + kh * 16));
                        bl[p*2][0] = r4[0]; bl[p*2][1] = r4[1];
                        bl[p*2+1][0] = r4[2]; bl[p*2+1][1] = r4[3];
                    }
                }
#pragma unroll
                for (int mt = 0; mt < MT; mt++)
#pragma unroll
                    for (int j = 0; j < 4; j++) {
                        const int nt = ntb * 4 + j;
                        mma_f16(acc[mt][nt], ah[mt], bh[j]);
                        if (NB == 2) mma_f16(acc[mt][nt], ah[mt], bl[j]);
                        if (NA == 2) mma_f16(acc[mt][nt], al[mt], bh[j]);
                    }
            }
        }
        __syncthreads();
    }

    const int fr = lane >> 2, fc = lane & 3;
#pragma unroll
    for (int mt = 0; mt < MT; mt++) {
        int row0 = bm + wm + mt * 16 + fr;
#pragma unroll
        for (int nt = 0; nt < NT; nt++) {
            int col = bn + wn + nt * 8 + 2 * fc;
#pragma unroll
            for (int h = 0; h < 2; h++) {
                int rr = row0 + h * 8;
                float v0 = acc[mt][nt][h * 2 + 0];
                float v1 = acc[mt][nt][h * 2 + 1];
                if (BIAS) { v0 += bias[col]; v1 += bias[col + 1]; }
                if (GELU) {
                    v0 = 0.5f * v0 * (1.f + erff(v0 * 0.70710678118654752f));
                    v1 = 0.5f * v1 * (1.f + erff(v1 * 0.70710678118654752f));
                }
                if (RES) {
                    v0 += res[(size_t)rr * N + col];
                    v1 += res[(size_t)rr * N + col + 1];
                }
                if (OSPLIT) {
                    __half h0, l0, h1, l1;
                    split_h(v0, h0, l0);
                    split_h(v1, h1, l1);
                    *(__half2*)(Oh + (size_t)rr * N + col) = __halves2half2(h0, h1);
                    *(__half2*)(Ol + (size_t)rr * N + col) = __halves2half2(l0, l1);
                } else if (!NGUARD) {
                    *(float2*)&Cp[(size_t)rr * N + col] = make_float2(v0, v1);
                } else {
                    if (col < N)     Cp[(size_t)rr * N + col]     = v0;
                    if (col + 1 < N) Cp[(size_t)rr * N + col + 1] = v1;
                }
            }
        }
    }
}

// ---------------------------------------------------------------------------
// Causal attention, TK=64 k-tiles, padded (stride-68) smem; split fp16 out.
// Dynamic smem: 4*64*68 + 64*4 floats = 70656 B.
// ---------------------------------------------------------------------------
#define APAD 68
__global__ __launch_bounds__(256) void attn_k(const float* __restrict__ QKV,
                                              __half* __restrict__ Oh,
                                              __half* __restrict__ Ol)
{
    extern __shared__ float as_[];
    float* Qs  = as_;                    // [64][68]
    float* Kt  = as_ + 64 * APAD;        // [64][68]  Kt[d][c]
    float* Vs  = as_ + 2 * 64 * APAD;    // [64][68]  Vs[c][d]
    float* Ps  = as_ + 3 * 64 * APAD;    // [64][68]
    float* red = as_ + 4 * 64 * APAD;    // [64][4]

    int tid = threadIdx.x;
    int qt = blockIdx.x, h = blockIdx.y, b = blockIdx.z;
    int r  = tid >> 2;                   // 0..63
    int q4 = tid & 3;                    // 0..3 -> cols q4*16..+15
    int qi = qt * 64 + r;

    const size_t rstride = 3 * EE;
    const float* qkvb = QKV + (size_t)b * SS * rstride;

    for (int i = tid; i < 64 * 64; i += 256) {
        int rr = i >> 6, d = i & 63;
        Qs[rr * APAD + d] = qkvb[(size_t)(qt * 64 + rr) * rstride + h * DD + d];
    }

    float m = -INFINITY, l = 0.f;
    float o[16];
#pragma unroll
    for (int j = 0; j < 16; j++) o[j] = 0.f;
    const float scale = 0.125f;

    int nkt = qt + 1;
    for (int kt = 0; kt < nkt; kt++) {
        __syncthreads();
        for (int i = tid; i < 64 * 64; i += 256) {
            int rr = i >> 6, d = i & 63;
            size_t base = (size_t)(kt * 64 + rr) * rstride + h * DD + d;
            Kt[d * APAD + rr] = qkvb[EE + base];
            Vs[rr * APAD + d] = qkvb[2 * EE + base];
        }
        __syncthreads();

        float sc[16];
#pragma unroll
        for (int j = 0; j < 16; j++) sc[j] = 0.f;
#pragma unroll 4
        for (int d = 0; d < 64; d++) {
            float qv = Qs[r * APAD + d];
            const float* kp = Kt + d * APAD + q4 * 16;
            float4 k0 = *(const float4*)(kp + 0);
            float4 k1 = *(const float4*)(kp + 4);
            float4 k2 = *(const float4*)(kp + 8);
            float4 k3 = *(const float4*)(kp + 12);
            sc[0]  = fmaf(qv, k0.x, sc[0]);  sc[1]  = fmaf(qv, k0.y, sc[1]);
            sc[2]  = fmaf(qv, k0.z, sc[2]);  sc[3]  = fmaf(qv, k0.w, sc[3]);
            sc[4]  = fmaf(qv, k1.x, sc[4]);  sc[5]  = fmaf(qv, k1.y, sc[5]);
            sc[6]  = fmaf(qv, k1.z, sc[6]);  sc[7]  = fmaf(qv, k1.w, sc[7]);
            sc[8]  = fmaf(qv, k2.x, sc[8]);  sc[9]  = fmaf(qv, k2.y, sc[9]);
            sc[10] = fmaf(qv, k2.z, sc[10]); sc[11] = fmaf(qv, k2.w, sc[11]);
            sc[12] = fmaf(qv, k3.x, sc[12]); sc[13] = fmaf(qv, k3.y, sc[13]);
            sc[14] = fmaf(qv, k3.z, sc[14]); sc[15] = fmaf(qv, k3.w, sc[15]);
        }
        float lmax = -INFINITY;
#pragma unroll
        for (int j = 0; j < 16; j++) {
            int kg = kt * 64 + q4 * 16 + j;
            sc[j] = (kg <= qi) ? sc[j] * scale : -1e30f;
            lmax = fmaxf(lmax, sc[j]);
        }
        red[r * 4 + q4] = lmax;
        __syncthreads();
        float mnew = fmaxf(fmaxf(fmaxf(red[r * 4 + 0], red[r * 4 + 1]),
                                 fmaxf(red[r * 4 + 2], red[r * 4 + 3])), m);
        __syncthreads();

        float lsum = 0.f;
#pragma unroll
        for (int j = 0; j < 16; j++) {
            float p = __expf(sc[j] - mnew);
            Ps[r * APAD + q4 * 16 + j] = p;
            lsum += p;
        }
        red[r * 4 + q4] = lsum;
        __syncthreads();
        float tsum = red[r * 4 + 0] + red[r * 4 + 1] + red[r * 4 + 2] + red[r * 4 + 3];
        float fac = __expf(m - mnew);
        l = l * fac + tsum;
        m = mnew;
#pragma unroll
        for (int j = 0; j < 16; j++) o[j] *= fac;

#pragma unroll 4
        for (int c = 0; c < 64; c++) {
            float p = Ps[r * APAD + c];
            const float* vp = Vs + c * APAD + q4 * 16;
            float4 v0 = *(const float4*)(vp + 0);
            float4 v1 = *(const float4*)(vp + 4);
            float4 v2 = *(const float4*)(vp + 8);
            float4 v3 = *(const float4*)(vp + 12);
            o[0]  = fmaf(p, v0.x, o[0]);  o[1]  = fmaf(p, v0.y, o[1]);
            o[2]  = fmaf(p, v0.z, o[2]);  o[3]  = fmaf(p, v0.w, o[3]);
            o[4]  = fmaf(p, v1.x, o[4]);  o[5]  = fmaf(p, v1.y, o[5]);
            o[6]  = fmaf(p, v1.z, o[6]);  o[7]  = fmaf(p, v1.w, o[7]);
            o[8]  = fmaf(p, v2.x, o[8]);  o[9]  = fmaf(p, v2.y, o[9]);
            o[10] = fmaf(p, v2.z, o[10]); o[11] = fmaf(p, v2.w, o[11]);
            o[12] = fmaf(p, v3.x, o[12]); o[13] = fmaf(p, v3.y, o[13]);
            o[14] = fmaf(p, v3.z, o[14]); o[15] = fmaf(p, v3.w, o[15]);
        }
    }

    float inv = 1.f / l;
    size_t obase = ((size_t)b * SS + qi) * EE + h * DD + q4 * 16;
#pragma unroll
    for (int j = 0; j < 16; j++) {
        __half hi, lo;
        split_h(o[j] * inv, hi, lo);
        Oh[obase + j] = hi;
        Ol[obase + j] = lo;
    }
}

// ---------------------------------------------------------------------------
// Host launcher
// ---------------------------------------------------------------------------
extern "C" void kernel_launch(void* const* d_in, const int* in_sizes, int n_in,
                              void* d_out, int out_size)
{
    const int*   tok    = (const int*)  d_in[0];
    const float* wte    = (const float*)d_in[1];
    const float* wpe    = (const float*)d_in[2];
    const float* ln1_g  = (const float*)d_in[3];
    const float* ln1_b  = (const float*)d_in[4];
    const float* attn_w = (const float*)d_in[5];
    const float* attn_b = (const float*)d_in[6];
    const float* proj_w = (const float*)d_in[7];
    const float* proj_b = (const float*)d_in[8];
    const float* ln2_g  = (const float*)d_in[9];
    const float* ln2_b  = (const float*)d_in[10];
    const float* fc_w   = (const float*)d_in[11];
    const float* fc_b   = (const float*)d_in[12];
    const float* fc2_w  = (const float*)d_in[13];
    const float* fc2_b  = (const float*)d_in[14];
    const float* lnf_g  = (const float*)d_in[15];
    const float* lnf_b  = (const float*)d_in[16];
    const float* lm_w   = (const float*)d_in[17];
    float* out = (float*)d_out;

    float *X, *QKV, *P;
    __half *Ah, *Al, *Fh, *Fl, *Wh, *Wl, *LMW;
    cudaGetSymbolAddress((void**)&X,   g_X);
    cudaGetSymbolAddress((void**)&QKV, g_QKV);
    cudaGetSymbolAddress((void**)&P,   g_P);
    cudaGetSymbolAddress((void**)&Ah,  g_Ah);
    cudaGetSymbolAddress((void**)&Al,  g_Al);
    cudaGetSymbolAddress((void**)&Fh,  g_Fh);
    cudaGetSymbolAddress((void**)&Fl,  g_Fl);
    cudaGetSymbolAddress((void**)&Wh,  g_Wh);
    cudaGetSymbolAddress((void**)&Wl,  g_Wl);
    cudaGetSymbolAddress((void**)&LMW, g_LMW);

    // GEMM configs (per-GEMM best):
    //  qkv: 128x256, 32x64 warp tiles, 512 thr (measured 66.5us)
    //  fc1/proj: 128x128, 32x32, 512 thr
    //  fc2: 128x128 split-K=3 partials (no epilogue), then redadd
    //  LM:  128x256, 2-term (A split, B fp16)
    auto qkv_f  = hgemm<128,256,32,64,2,2,2, true,false,false,false,false,false>;
    auto fc1_f  = hgemm<128,128,32,32,2,2,2, true,true, false,false,true, false>;
    auto projr_f= hgemm<128,128,32,32,2,2,2, true,false,true, false,false,false>;
    auto fc2p_f = hgemm<128,128,32,32,2,2,2, false,false,false,false,false,true>;
    auto lm_f   = hgemm<128,256,32,64,2,1,2, false,false,false,true,false,false>;

    const int SM_BIG = 2 * (2*128 + 2*256) * RS * 2;    // 122880 B
    const int SM_LAY = 2 * (2*128 + 2*128) * RS * 2;    //  81920 B
    const int SM_LM  = 2 * (2*128 + 1*256) * RS * 2;    //  81920 B
    const int SM_ATT = (4 * 64 * APAD + 64 * 4) * 4;    //  70656 B
    cudaFuncSetAttribute(qkv_f,  cudaFuncAttributeMaxDynamicSharedMemorySize, SM_BIG);
    cudaFuncSetAttribute(fc1_f,  cudaFuncAttributeMaxDynamicSharedMemorySize, SM_LAY);
    cudaFuncSetAttribute(projr_f,cudaFuncAttributeMaxDynamicSharedMemorySize, SM_LAY);
    cudaFuncSetAttribute(fc2p_f, cudaFuncAttributeMaxDynamicSharedMemorySize, SM_LAY);
    cudaFuncSetAttribute(lm_f,   cudaFuncAttributeMaxDynamicSharedMemorySize, SM_LM);
    cudaFuncSetAttribute(attn_k, cudaFuncAttributeMaxDynamicSharedMemorySize, SM_ATT);

    embed_k<<<MM, 256>>>(tok, wte, wpe, X);

    for (int i = 0; i < LL; i++) {
        // LN1 -> split
        ln_split_k<<<MM, 256>>>(X, ln1_g + i * EE, ln1_b + i * EE, Ah, Al);
        // QKV = A @ attn_w + b    [2048 x 2304]
        splitT3_k<<<dim3(3 * EE / 32, EE / 32), dim3(32, 8)>>>(
            attn_w + (size_t)i * EE * 3 * EE, Wh, Wl, EE, 3 * EE);
        qkv_f<<<dim3(MM / 128, 3 * EE / 256), 512, SM_BIG>>>(
            Ah, Al, Wh, Wl, attn_b + (size_t)i * 3 * EE, nullptr,
            QKV, nullptr, nullptr, 3 * EE, EE, EE);
        // attention -> split
        attn_k<<<dim3(SS / 64, HH, BB), 256, SM_ATT>>>(QKV, Ah, Al);
        // X += A @ proj_w + b     [2048 x 768]
        splitT3_k<<<dim3(EE / 32, EE / 32), dim3(32, 8)>>>(
            proj_w + (size_t)i * EE * EE, Wh, Wl, EE, EE);
        projr_f<<<dim3(MM / 128, EE / 128), 512, SM_LAY>>>(
            Ah, Al, Wh, Wl, proj_b + (size_t)i * EE, X,
            X, nullptr, nullptr, EE, EE, EE);
        // LN2 -> split
        ln_split_k<<<MM, 256>>>(X, ln2_g + i * EE, ln2_b + i * EE, Ah, Al);
        // F = gelu(A @ fc_w + b) -> split   [2048 x 3072]
        splitT3_k<<<dim3(4 * EE / 32, EE / 32), dim3(32, 8)>>>(
            fc_w + (size_t)i * EE * 4 * EE, Wh, Wl, EE, 4 * EE);
        fc1_f<<<dim3(MM / 128, 4 * EE / 128), 512, SM_LAY>>>(
            Ah, Al, Wh, Wl, fc_b + (size_t)i * 4 * EE, nullptr,
            nullptr, Fh, Fl, 4 * EE, EE, EE);
        // FC2 split-K=3 partials: P[z] = F @ fc2_w (K-part z), then reduce
        splitT3_k<<<dim3(EE / 32, 4 * EE / 32), dim3(32, 8)>>>(
            fc2_w + (size_t)i * 4 * EE * EE, Wh, Wl, 4 * EE, EE);
        fc2p_f<<<dim3(MM / 128, EE / 128, 3), 512, SM_LAY>>>(
            Fh, Fl, Wh, Wl, nullptr, nullptr,
            P, nullptr, nullptr, EE, 4 * EE, 1024);
        redadd_k<<<(MM * EE + 255) / 256, 256>>>(P, fc2_b + (size_t)i * EE, X);
    }

    // final LN -> split, LM head (2-term: A split, B fp16; guarded stores)
    ln_split_k<<<MM, 256>>>(X, lnf_g, lnf_b, Ah, Al);
    splitT1_k<<<dim3(NPADLM / 32, EE / 32), dim3(32, 8)>>>(lm_w, LMW, EE, VV);
    lm_f<<<dim3(MM / 128, NPADLM / 256), 512, SM_LM>>>(
        Ah, Al, LMW, nullptr, nullptr, nullptr,
        out, nullptr, nullptr, VV, EE, EE);
}

// round 16
// speedup vs baseline: 1.8182x; 1.8182x over previous
#include <cuda_runtime.h>
#include <cuda_fp16.h>
#include <math.h>
#include <stdint.h>

// ---------------------------------------------------------------------------
// GPT-2 small forward:  B=2, S=1024, L=4, H=12, E=768, D=64, V=50257
// All GEMMs + attention on mma.sync.m16n8k16.f16 with fp16 split operands:
//   layer GEMMs + attention matmuls: 3-term split, err ~2^-22
//   LM head: 2-term (A split, B fp16), verified 2.08e-4
// ---------------------------------------------------------------------------
#define BB 2
#define SS 1024
#define LL 4
#define HH 12
#define EE 768
#define VV 50257
#define DD 64
#define MM (BB*SS)
#define NPADLM 50432
#define QS (3*EE)

// Scratch (device globals: allocation-free rule)
__device__ float g_X  [MM * EE];
__device__ __align__(256) __half g_Ah[MM * EE];
__device__ __align__(256) __half g_Al[MM * EE];
__device__ __align__(256) __half g_Fh[MM * 4 * EE];   // QKV split / FC1 split
__device__ __align__(256) __half g_Fl[MM * 4 * EE];
__device__ __align__(256) __half g_Wh[4 * EE * EE];
__device__ __align__(256) __half g_Wl[4 * EE * EE];
__device__ __align__(256) __half g_LMW[(size_t)NPADLM * EE];

// ---------------------------------------------------------------------------
__device__ __forceinline__ uint32_t smem_u32(const void* p) {
    return (uint32_t)__cvta_generic_to_shared(p);
}
__device__ __forceinline__ void cp16(uint32_t dst, const void* src) {
    asm volatile("cp.async.cg.shared.global [%0], [%1], 16;" :: "r"(dst), "l"(src));
}
__device__ __forceinline__ void mma_f16(float* c, const uint32_t* a, const uint32_t* b) {
    asm volatile(
        "mma.sync.aligned.m16n8k16.row.col.f32.f16.f16.f32 "
        "{%0,%1,%2,%3},{%4,%5,%6,%7},{%8,%9},{%0,%1,%2,%3};"
        : "+f"(c[0]), "+f"(c[1]), "+f"(c[2]), "+f"(c[3])
        : "r"(a[0]), "r"(a[1]), "r"(a[2]), "r"(a[3]), "r"(b[0]), "r"(b[1]));
}
__device__ __forceinline__ void ldmx4(uint32_t* r, uint32_t addr) {
    asm volatile("ldmatrix.sync.aligned.m8n8.x4.shared.b16 {%0,%1,%2,%3}, [%4];"
                 : "=r"(r[0]), "=r"(r[1]), "=r"(r[2]), "=r"(r[3]) : "r"(addr));
}
__device__ __forceinline__ void ldmx4t(uint32_t* r, uint32_t addr) {
    asm volatile("ldmatrix.sync.aligned.m8n8.x4.trans.shared.b16 {%0,%1,%2,%3}, [%4];"
                 : "=r"(r[0]), "=r"(r[1]), "=r"(r[2]), "=r"(r[3]) : "r"(addr));
}
__device__ __forceinline__ void split_h(float v, __half& hi, __half& lo) {
    hi = __float2half(v);
    lo = __float2half(v - __half2float(hi));
}
__device__ __forceinline__ uint32_t pack2(__half a, __half b) {
    __half2 t = __halves2half2(a, b);
    return *(uint32_t*)&t;
}

// ---------------------------------------------------------------------------
// Embedding
// ---------------------------------------------------------------------------
__global__ void embed_k(const int* __restrict__ tok,
                        const float* __restrict__ wte,
                        const float* __restrict__ wpe,
                        float* __restrict__ X)
{
    int row = blockIdx.x;
    int s   = row & (SS - 1);
    int t   = tok[row];
    const float* we = wte + (size_t)t * EE;
    const float* wp = wpe + (size_t)s * EE;
    float* xr = X + (size_t)row * EE;
    for (int e = threadIdx.x; e < EE; e += blockDim.x)
        xr[e] = we[e] + wp[e];
}

// ---------------------------------------------------------------------------
// LayerNorm -> split fp16 hi/lo
// ---------------------------------------------------------------------------
__global__ __launch_bounds__(256) void ln_split_k(const float* __restrict__ X,
                                                  const float* __restrict__ gam,
                                                  const float* __restrict__ bet,
                                                  __half* __restrict__ Oh,
                                                  __half* __restrict__ Ol)
{
    __shared__ float s1[8], s2[8];
    int row = blockIdx.x, tid = threadIdx.x;
    const float* xr = X + (size_t)row * EE;
    float v[3];
    float sum = 0.f, sq = 0.f;
#pragma unroll
    for (int k = 0; k < 3; k++) {
        v[k] = xr[tid + k * 256];
        sum += v[k];
        sq  += v[k] * v[k];
    }
#pragma unroll
    for (int o = 16; o > 0; o >>= 1) {
        sum += __shfl_xor_sync(0xffffffffu, sum, o);
        sq  += __shfl_xor_sync(0xffffffffu, sq,  o);
    }
    if ((tid & 31) == 0) { s1[tid >> 5] = sum; s2[tid >> 5] = sq; }
    __syncthreads();
    sum = 0.f; sq = 0.f;
#pragma unroll
    for (int i = 0; i < 8; i++) { sum += s1[i]; sq += s2[i]; }
    const float inv_n = 1.0f / (float)EE;
    float mu  = sum * inv_n;
    float var = sq * inv_n - mu * mu;
    float rs  = rsqrtf(var + 1e-5f);
#pragma unroll
    for (int k = 0; k < 3; k++) {
        int e = tid + k * 256;
        float y = (v[k] - mu) * rs * gam[e] + bet[e];
        __half hi, lo; split_h(y, hi, lo);
        Oh[(size_t)row * EE + e] = hi;
        Ol[(size_t)row * EE + e] = lo;
    }
}

// ---------------------------------------------------------------------------
// Weight split+transpose: Bg[K,N] fp32 -> Bh,Bl [N,K] fp16
// ---------------------------------------------------------------------------
__global__ void splitT3_k(const float* __restrict__ Bg,
                          __half* __restrict__ Bh,
                          __half* __restrict__ Bl, int K, int N)
{
    __shared__ float t[32][33];
    int n0 = blockIdx.x * 32, k0 = blockIdx.y * 32;
    int tx = threadIdx.x, ty = threadIdx.y;
#pragma unroll
    for (int i = 0; i < 4; i++)
        t[ty + 8 * i][tx] = Bg[(size_t)(k0 + ty + 8 * i) * N + n0 + tx];
    __syncthreads();
#pragma unroll
    for (int i = 0; i < 4; i++) {
        int n = n0 + ty + 8 * i;
        int k = k0 + tx;
        __half hi, lo; split_h(t[tx][ty + 8 * i], hi, lo);
        Bh[(size_t)n * K + k] = hi;
        Bl[(size_t)n * K + k] = lo;
    }
}

// Single-fp16 transpose with zero pad (LM head weights)
__global__ void splitT1_k(const float* __restrict__ Bg,
                          __half* __restrict__ Bo, int K, int N)
{
    __shared__ float t[32][33];
    int n0 = blockIdx.x * 32, k0 = blockIdx.y * 32;
    int tx = threadIdx.x, ty = threadIdx.y;
#pragma unroll
    for (int i = 0; i < 4; i++) {
        int n = n0 + tx;
        t[ty + 8 * i][tx] = (n < N) ? Bg[(size_t)(k0 + ty + 8 * i) * N + n] : 0.f;
    }
    __syncthreads();
#pragma unroll
    for (int i = 0; i < 4; i++) {
        int n = n0 + ty + 8 * i;
        Bo[(size_t)n * K + k0 + tx] = __float2half(t[tx][ty + 8 * i]);
    }
}

// ---------------------------------------------------------------------------
// fp16-split GEMM: C[M,N] = A[M,K] @ W[N,K]^T  (as in R14/R15, SPLITK unused)
// ---------------------------------------------------------------------------
#define RS 40
#define KC 32

template<int BM, int BN, int WM, int WN, int NA, int NB, int NSTG,
         bool BIAS, bool GELU, bool RES, bool NGUARD, bool OSPLIT>
__global__ void __launch_bounds__(((BM/WM)*(BN/WN))*32)
hgemm(const __half* __restrict__ Ah, const __half* __restrict__ Al,
      const __half* __restrict__ Bh, const __half* __restrict__ Bl,
      const float* __restrict__ bias, const float* __restrict__ res,
      float* __restrict__ C, __half* __restrict__ Oh, __half* __restrict__ Ol,
      int N, int K)
{
    constexpr int WARPS_M = BM / WM;
    constexpr int NTHR = WARPS_M * (BN / WN) * 32;
    constexpr int MT = WM / 16, NT = WN / 8;
    constexpr int STG = (NA * BM + NB * BN) * RS;
    constexpr int OAl = BM * RS;
    constexpr int OBh = NA * BM * RS;
    constexpr int OBl = NA * BM * RS + BN * RS;
    constexpr int CH  = (NA * BM + NB * BN) * 4;

    extern __shared__ __half sm[];

    const int tid = threadIdx.x, lane = tid & 31, wid = tid >> 5;
    const int wm = (wid % WARPS_M) * WM, wn = (wid / WARPS_M) * WN;
    const int bm = blockIdx.x * BM, bn = blockIdx.y * BN;

    float acc[MT][NT][4];
#pragma unroll
    for (int i = 0; i < MT; i++)
#pragma unroll
        for (int j = 0; j < NT; j++)
#pragma unroll
            for (int t = 0; t < 4; t++) acc[i][j][t] = 0.f;

    const int nIter = K / KC;

    auto load_stage = [&](int it, int s) {
        const int k0 = it * KC;
#pragma unroll
        for (int t = 0; t < CH / NTHR; t++) {
            int c = tid + t * NTHR;
            int ridx = c >> 2, part = c & 3;
            const __half* g; int off;
            if (NA == 2 && ridx < BM)      { g = Ah + (size_t)(bm + ridx) * K; off = ridx * RS; }
            else if (NA == 2 && ridx < 2 * BM)
                { int r = ridx - BM; g = Al + (size_t)(bm + r) * K; off = OAl + r * RS; }
            else if (NA == 1 && ridx < BM) { g = Ah + (size_t)(bm + ridx) * K; off = ridx * RS; }
            else if (NB == 1 || ridx < NA * BM + BN)
                { int r = ridx - NA * BM; g = Bh + (size_t)(bn + r) * K; off = OBh + r * RS; }
            else
                { int r = ridx - NA * BM - BN; g = Bl + (size_t)(bn + r) * K; off = OBl + r * RS; }
            cp16(smem_u32(sm + s * STG + off + part * 8), g + k0 + part * 8);
        }
        asm volatile("cp.async.commit_group;");
    };

#pragma unroll
    for (int c = 0; c < NSTG - 1; c++) load_stage(c, c);

    const int a_lane = (wm + (lane & 15)) * RS + ((lane >> 4) << 3);
    const int b_lane = (wn + ((lane >> 4) << 3) + (lane & 7)) * RS + (((lane >> 3) & 1) << 3);

    for (int it = 0; it < nIter; it++) {
        const int s = it % NSTG;
        asm volatile("cp.async.wait_group %0;" :: "n"(NSTG - 2));
        __syncthreads();
        if (it + NSTG - 1 < nIter)
            load_stage(it + NSTG - 1, (it + NSTG - 1) % NSTG);

        const __half* stg = sm + s * STG;
#pragma unroll
        for (int kh = 0; kh < 2; kh++) {
            uint32_t ah[MT][4], al[MT][4];
#pragma unroll
            for (int mt = 0; mt < MT; mt++) {
                ldmx4(ah[mt], smem_u32(stg + a_lane + mt * 16 * RS + kh * 16));
                if (NA == 2)
                    ldmx4(al[mt], smem_u32(stg + OAl + a_lane + mt * 16 * RS + kh * 16));
            }
#pragma unroll
            for (int ntb = 0; ntb < NT / 4; ntb++) {
                uint32_t bh[4][2], bl[4][2];
#pragma unroll
                for (int p = 0; p < 2; p++) {
                    const int nt = ntb * 4 + p * 2;
                    uint32_t r4[4];
                    ldmx4(r4, smem_u32(stg + OBh + b_lane + nt * 8 * RS + kh * 16));
                    bh[p*2][0] = r4[0]; bh[p*2][1] = r4[1];
                    bh[p*2+1][0] = r4[2]; bh[p*2+1][1] = r4[3];
                    if (NB == 2) {
                        ldmx4(r4, smem_u32(stg + OBl + b_lane + nt * 8 * RS + kh * 16));
                        bl[p*2][0] = r4[0]; bl[p*2][1] = r4[1];
                        bl[p*2+1][0] = r4[2]; bl[p*2+1][1] = r4[3];
                    }
                }
#pragma unroll
                for (int mt = 0; mt < MT; mt++)
#pragma unroll
                    for (int j = 0; j < 4; j++) {
                        const int nt = ntb * 4 + j;
                        mma_f16(acc[mt][nt], ah[mt], bh[j]);
                        if (NB == 2) mma_f16(acc[mt][nt], ah[mt], bl[j]);
                        if (NA == 2) mma_f16(acc[mt][nt], al[mt], bh[j]);
                    }
            }
        }
        __syncthreads();
    }

    const int fr = lane >> 2, fc = lane & 3;
#pragma unroll
    for (int mt = 0; mt < MT; mt++) {
        int row0 = bm + wm + mt * 16 + fr;
#pragma unroll
        for (int nt = 0; nt < NT; nt++) {
            int col = bn + wn + nt * 8 + 2 * fc;
#pragma unroll
            for (int h = 0; h < 2; h++) {
                int rr = row0 + h * 8;
                float v0 = acc[mt][nt][h * 2 + 0];
                float v1 = acc[mt][nt][h * 2 + 1];
                if (BIAS) { v0 += bias[col]; v1 += bias[col + 1]; }
                if (GELU) {
                    v0 = 0.5f * v0 * (1.f + erff(v0 * 0.70710678118654752f));
                    v1 = 0.5f * v1 * (1.f + erff(v1 * 0.70710678118654752f));
                }
                if (RES) {
                    v0 += res[(size_t)rr * N + col];
                    v1 += res[(size_t)rr * N + col + 1];
                }
                if (OSPLIT) {
                    __half h0, l0, h1, l1;
                    split_h(v0, h0, l0);
                    split_h(v1, h1, l1);
                    *(__half2*)(Oh + (size_t)rr * N + col) = __halves2half2(h0, h1);
                    *(__half2*)(Ol + (size_t)rr * N + col) = __halves2half2(l0, l1);
                } else if (!NGUARD) {
                    *(float2*)&C[(size_t)rr * N + col] = make_float2(v0, v1);
                } else {
                    if (col < N)     C[(size_t)rr * N + col]     = v0;
                    if (col + 1 < N) C[(size_t)rr * N + col + 1] = v1;
                }
            }
        }
    }
}

// ---------------------------------------------------------------------------
// Tensor-core flash attention.
// Block = (128 queries, head, batch), 8 warps; each warp owns 16 full rows.
// Q frags in registers (hi/lo); per 64-key tile: S = Q@K^T (3-term mma),
// in-register online softmax (shfl-only), P->A-frags in registers,
// O += P@V (3-term, V via ldmatrix.trans). Output split fp16 to Ah/Al.
// ---------------------------------------------------------------------------
#define RSV 72
__global__ __launch_bounds__(256) void attn_k(const __half* __restrict__ Fh,
                                              const __half* __restrict__ Fl,
                                              __half* __restrict__ Oh,
                                              __half* __restrict__ Ol)
{
    extern __shared__ __half sma[];
    __half* Ksh = sma;
    __half* Ksl = sma + 64 * RSV;
    __half* Vsh = sma + 2 * 64 * RSV;
    __half* Vsl = sma + 3 * 64 * RSV;

    const int tid = threadIdx.x, lane = tid & 31, wid = tid >> 5;
    const int fr = lane >> 2, fc = lane & 3;
    const int qt = blockIdx.x, h = blockIdx.y, b = blockIdx.z;
    const int qrow = qt * 128 + wid * 16;     // within-sequence
    const int grow0 = qrow + fr;

    const __half* Fhb = Fh + (size_t)b * SS * QS;
    const __half* Flb = Fl + (size_t)b * SS * QS;

    // Q fragments (a0..a3 per k-chunk), hi and lo
    uint32_t qfh[4][4], qfl[4][4];
#pragma unroll
    for (int kc = 0; kc < 4; kc++)
#pragma unroll
        for (int j = 0; j < 4; j++) {
            int row = qrow + fr + (j & 1) * 8;
            int col = h * DD + kc * 16 + 2 * fc + (j >> 1) * 8;
            qfh[kc][j] = *(const uint32_t*)&Fhb[(size_t)row * QS + col];
            qfl[kc][j] = *(const uint32_t*)&Flb[(size_t)row * QS + col];
        }

    float o[8][4];
#pragma unroll
    for (int nt = 0; nt < 8; nt++)
#pragma unroll
        for (int j = 0; j < 4; j++) o[nt][j] = 0.f;
    float m0 = -INFINITY, m1 = -INFINITY, l0 = 0.f, l1 = 0.f;

    const int nkt = 2 * qt + 2;
    for (int kt = 0; kt < nkt; kt++) {
        __syncthreads();
        // Load K/V hi/lo tiles (64 rows x 64 halfs each)
#pragma unroll
        for (int t = 0; t < 8; t++) {
            int c = tid + t * 256;
            int arr = c >> 9, row = (c >> 3) & 63, part = c & 7;
            const __half* src;
            __half* dstb;
            size_t gro = (size_t)(kt * 64 + row) * QS + h * DD;
            if (arr == 0)      { src = Fhb + gro + EE;     dstb = Ksh; }
            else if (arr == 1) { src = Flb + gro + EE;     dstb = Ksl; }
            else if (arr == 2) { src = Fhb + gro + 2 * EE; dstb = Vsh; }
            else               { src = Flb + gro + 2 * EE; dstb = Vsl; }
            cp16(smem_u32(dstb + row * RSV + part * 8), src + part * 8);
        }
        asm volatile("cp.async.commit_group;");
        asm volatile("cp.async.wait_group 0;");
        __syncthreads();

        // S = Q @ K^T  (3-term)
        float s[8][4];
#pragma unroll
        for (int nt = 0; nt < 8; nt++)
#pragma unroll
            for (int j = 0; j < 4; j++) s[nt][j] = 0.f;
#pragma unroll
        for (int kc = 0; kc < 4; kc++)
#pragma unroll
            for (int np = 0; np < 4; np++) {
                uint32_t kbh[4], kbl[4];
                uint32_t off = (np * 16 + (lane & 7) + ((lane >> 4) << 3)) * RSV
                             + kc * 16 + (((lane >> 3) & 1) << 3);
                ldmx4(kbh, smem_u32(Ksh + off));
                ldmx4(kbl, smem_u32(Ksl + off));
                mma_f16(s[2*np],   qfh[kc], kbh);
                mma_f16(s[2*np],   qfh[kc], kbl);
                mma_f16(s[2*np],   qfl[kc], kbh);
                mma_f16(s[2*np+1], qfh[kc], kbh + 2);
                mma_f16(s[2*np+1], qfh[kc], kbl + 2);
                mma_f16(s[2*np+1], qfl[kc], kbh + 2);
            }

        // scale + causal mask + online softmax (rows owned per-warp)
        const bool needm = (kt >= 2 * qt);
        float r0 = -INFINITY, r1 = -INFINITY;
#pragma unroll
        for (int nt = 0; nt < 8; nt++)
#pragma unroll
            for (int j = 0; j < 4; j++) {
                float v = s[nt][j] * 0.125f;
                if (needm) {
                    int colg = kt * 64 + nt * 8 + 2 * fc + (j & 1);
                    int rowg = grow0 + (j >> 1) * 8;
                    if (colg > rowg) v = -1e30f;
                }
                s[nt][j] = v;
                if (j < 2) r0 = fmaxf(r0, v); else r1 = fmaxf(r1, v);
            }
        r0 = fmaxf(r0, __shfl_xor_sync(0xffffffffu, r0, 1));
        r0 = fmaxf(r0, __shfl_xor_sync(0xffffffffu, r0, 2));
        r1 = fmaxf(r1, __shfl_xor_sync(0xffffffffu, r1, 1));
        r1 = fmaxf(r1, __shfl_xor_sync(0xffffffffu, r1, 2));
        float mn0 = fmaxf(m0, r0), mn1 = fmaxf(m1, r1);
        float fac0 = __expf(m0 - mn0), fac1 = __expf(m1 - mn1);
        m0 = mn0; m1 = mn1;
        float ls0 = 0.f, ls1 = 0.f;
#pragma unroll
        for (int nt = 0; nt < 8; nt++)
#pragma unroll
            for (int j = 0; j < 4; j++) {
                float p = __expf(s[nt][j] - ((j < 2) ? mn0 : mn1));
                s[nt][j] = p;
                if (j < 2) ls0 += p; else ls1 += p;
            }
        ls0 += __shfl_xor_sync(0xffffffffu, ls0, 1);
        ls0 += __shfl_xor_sync(0xffffffffu, ls0, 2);
        ls1 += __shfl_xor_sync(0xffffffffu, ls1, 1);
        ls1 += __shfl_xor_sync(0xffffffffu, ls1, 2);
        l0 = l0 * fac0 + ls0;
        l1 = l1 * fac1 + ls1;
#pragma unroll
        for (int nt = 0; nt < 8; nt++) {
            o[nt][0] *= fac0; o[nt][1] *= fac0;
            o[nt][2] *= fac1; o[nt][3] *= fac1;
        }

        // O += P @ V  (3-term; P frags built in registers from S tiles)
#pragma unroll
        for (int kc = 0; kc < 4; kc++) {
            uint32_t pah[4], pal[4];
            {
                __half h0, l0h, h1, l1h;
                split_h(s[2*kc][0], h0, l0h); split_h(s[2*kc][1], h1, l1h);
                pah[0] = pack2(h0, h1); pal[0] = pack2(l0h, l1h);
                split_h(s[2*kc][2], h0, l0h); split_h(s[2*kc][3], h1, l1h);
                pah[1] = pack2(h0, h1); pal[1] = pack2(l0h, l1h);
                split_h(s[2*kc+1][0], h0, l0h); split_h(s[2*kc+1][1], h1, l1h);
                pah[2] = pack2(h0, h1); pal[2] = pack2(l0h, l1h);
                split_h(s[2*kc+1][2], h0, l0h); split_h(s[2*kc+1][3], h1, l1h);
                pah[3] = pack2(h0, h1); pal[3] = pack2(l0h, l1h);
            }
#pragma unroll
            for (int np = 0; np < 4; np++) {
                uint32_t vbh[4], vbl[4];
                uint32_t off = (kc * 16 + (lane & 7) + (((lane >> 3) & 1) << 3)) * RSV
                             + np * 16 + ((lane >> 4) << 3);
                ldmx4t(vbh, smem_u32(Vsh + off));
                ldmx4t(vbl, smem_u32(Vsl + off));
                mma_f16(o[2*np],   pah, vbh);
                mma_f16(o[2*np],   pah, vbl);
                mma_f16(o[2*np],   pal, vbh);
                mma_f16(o[2*np+1], pah, vbh + 2);
                mma_f16(o[2*np+1], pah, vbl + 2);
                mma_f16(o[2*np+1], pal, vbh + 2);
            }
        }
    }

    // Normalize + split-fp16 store
    float inv0 = 1.f / l0, inv1 = 1.f / l1;
    size_t base0 = ((size_t)b * SS + grow0) * EE + h * DD;
    size_t base1 = base0 + (size_t)8 * EE;
#pragma unroll
    for (int nt = 0; nt < 8; nt++) {
        int col = nt * 8 + 2 * fc;
        __half h0, e0, h1, e1;
        split_h(o[nt][0] * inv0, h0, e0);
        split_h(o[nt][1] * inv0, h1, e1);
        *(__half2*)(Oh + base0 + col) = __halves2half2(h0, h1);
        *(__half2*)(Ol + base0 + col) = __halves2half2(e0, e1);
        split_h(o[nt][2] * inv1, h0, e0);
        split_h(o[nt][3] * inv1, h1, e1);
        *(__half2*)(Oh + base1 + col) = __halves2half2(h0, h1);
        *(__half2*)(Ol + base1 + col) = __halves2half2(e0, e1);
    }
}

// ---------------------------------------------------------------------------
// Host launcher
// ---------------------------------------------------------------------------
extern "C" void kernel_launch(void* const* d_in, const int* in_sizes, int n_in,
                              void* d_out, int out_size)
{
    const int*   tok    = (const int*)  d_in[0];
    const float* wte    = (const float*)d_in[1];
    const float* wpe    = (const float*)d_in[2];
    const float* ln1_g  = (const float*)d_in[3];
    const float* ln1_b  = (const float*)d_in[4];
    const float* attn_w = (const float*)d_in[5];
    const float* attn_b = (const float*)d_in[6];
    const float* proj_w = (const float*)d_in[7];
    const float* proj_b = (const float*)d_in[8];
    const float* ln2_g  = (const float*)d_in[9];
    const float* ln2_b  = (const float*)d_in[10];
    const float* fc_w   = (const float*)d_in[11];
    const float* fc_b   = (const float*)d_in[12];
    const float* fc2_w  = (const float*)d_in[13];
    const float* fc2_b  = (const float*)d_in[14];
    const float* lnf_g  = (const float*)d_in[15];
    const float* lnf_b  = (const float*)d_in[16];
    const float* lm_w   = (const float*)d_in[17];
    float* out = (float*)d_out;

    float *X;
    __half *Ah, *Al, *Fh, *Fl, *Wh, *Wl, *LMW;
    cudaGetSymbolAddress((void**)&X,   g_X);
    cudaGetSymbolAddress((void**)&Ah,  g_Ah);
    cudaGetSymbolAddress((void**)&Al,  g_Al);
    cudaGetSymbolAddress((void**)&Fh,  g_Fh);
    cudaGetSymbolAddress((void**)&Fl,  g_Fl);
    cudaGetSymbolAddress((void**)&Wh,  g_Wh);
    cudaGetSymbolAddress((void**)&Wl,  g_Wl);
    cudaGetSymbolAddress((void**)&LMW, g_LMW);

    // GEMM configs
    //  qkv: 128x256/32x64, OSPLIT -> Fh/Fl (measured-best mainloop)
    //  fc1: 128x128/32x32, GELU + OSPLIT -> Fh/Fl
    //  proj/fc2: 128x128/32x32, bias+residual -> X
    //  LM:  128x256/32x64, 2-term (A split, B fp16)
    auto qkv_f  = hgemm<128,256,32,64,2,2,2, true,false,false,false,true>;
    auto fc1_f  = hgemm<128,128,32,32,2,2,2, true,true, false,false,true>;
    auto layr_f = hgemm<128,128,32,32,2,2,2, true,false,true, false,false>;
    auto lm_f   = hgemm<128,256,32,64,2,1,2, false,false,false,true,false>;

    const int SM_BIG = 2 * (2*128 + 2*256) * RS * 2;    // 122880 B
    const int SM_LAY = 2 * (2*128 + 2*128) * RS * 2;    //  81920 B
    const int SM_LM  = 2 * (2*128 + 1*256) * RS * 2;    //  81920 B
    const int SM_ATT = 4 * 64 * RSV * 2;                //  36864 B
    cudaFuncSetAttribute(qkv_f,  cudaFuncAttributeMaxDynamicSharedMemorySize, SM_BIG);
    cudaFuncSetAttribute(fc1_f,  cudaFuncAttributeMaxDynamicSharedMemorySize, SM_LAY);
    cudaFuncSetAttribute(layr_f, cudaFuncAttributeMaxDynamicSharedMemorySize, SM_LAY);
    cudaFuncSetAttribute(lm_f,   cudaFuncAttributeMaxDynamicSharedMemorySize, SM_LM);
    cudaFuncSetAttribute(attn_k, cudaFuncAttributeMaxDynamicSharedMemorySize, SM_ATT);

    embed_k<<<MM, 256>>>(tok, wte, wpe, X);

    for (int i = 0; i < LL; i++) {
        // LN1 -> split
        ln_split_k<<<MM, 256>>>(X, ln1_g + i * EE, ln1_b + i * EE, Ah, Al);
        // QKV = A @ attn_w + b -> split fp16 (Fh/Fl)   [2048 x 2304]
        splitT3_k<<<dim3(3 * EE / 32, EE / 32), dim3(32, 8)>>>(
            attn_w + (size_t)i * EE * 3 * EE, Wh, Wl, EE, 3 * EE);
        qkv_f<<<dim3(MM / 128, 3 * EE / 256), 512, SM_BIG>>>(
            Ah, Al, Wh, Wl, attn_b + (size_t)i * 3 * EE, nullptr,
            nullptr, Fh, Fl, 3 * EE, EE);
        // tensor-core flash attention -> split (Ah/Al)
        attn_k<<<dim3(SS / 128, HH, BB), 256, SM_ATT>>>(Fh, Fl, Ah, Al);
        // X += A @ proj_w + b     [2048 x 768]
        splitT3_k<<<dim3(EE / 32, EE / 32), dim3(32, 8)>>>(
            proj_w + (size_t)i * EE * EE, Wh, Wl, EE, EE);
        layr_f<<<dim3(MM / 128, EE / 128), 512, SM_LAY>>>(
            Ah, Al, Wh, Wl, proj_b + (size_t)i * EE, X,
            X, nullptr, nullptr, EE, EE);
        // LN2 -> split
        ln_split_k<<<MM, 256>>>(X, ln2_g + i * EE, ln2_b + i * EE, Ah, Al);
        // F = gelu(A @ fc_w + b) -> split (Fh/Fl)   [2048 x 3072]
        splitT3_k<<<dim3(4 * EE / 32, EE / 32), dim3(32, 8)>>>(
            fc_w + (size_t)i * EE * 4 * EE, Wh, Wl, EE, 4 * EE);
        fc1_f<<<dim3(MM / 128, 4 * EE / 128), 512, SM_LAY>>>(
            Ah, Al, Wh, Wl, fc_b + (size_t)i * 4 * EE, nullptr,
            nullptr, Fh, Fl, 4 * EE, EE);
        // X += F @ fc2_w + b      [2048 x 768], K=3072
        splitT3_k<<<dim3(EE / 32, 4 * EE / 32), dim3(32, 8)>>>(
            fc2_w + (size_t)i * 4 * EE * EE, Wh, Wl, 4 * EE, EE);
        layr_f<<<dim3(MM / 128, EE / 128), 512, SM_LAY>>>(
            Fh, Fl, Wh, Wl, fc2_b + (size_t)i * EE, X,
            X, nullptr, nullptr, EE, 4 * EE);
    }

    // final LN -> split, LM head (2-term: A split, B fp16; guarded stores)
    ln_split_k<<<MM, 256>>>(X, lnf_g, lnf_b, Ah, Al);
    splitT1_k<<<dim3(NPADLM / 32, EE / 32), dim3(32, 8)>>>(lm_w, LMW, EE, VV);
    lm_f<<<dim3(MM / 128, NPADLM / 256), 512, SM_LM>>>(
        Ah, Al, LMW, nullptr, nullptr, nullptr,
        out, nullptr, nullptr, VV, EE);
}